// round 1
// baseline (speedup 1.0000x reference)
#include <cuda_runtime.h>
#include <math.h>

// ---------------- problem constants ----------------
#define cB    16
#define cCh   3
#define cHW   384
#define cP    16
#define cG    24
#define cNP   576          // G*G
#define cD    768
#define cFF   3072
#define cNH   12
#define cNL   12
#define cKsel 288          // top-K
#define cS    289          // K+1
#define cHD   64
#define cNCLS 1000
#define cM    (cB*cS)      // 4624 rows (b,s)
#define cMP   (cB*cNP)     // 9216 patch rows
#define cBH   (cB*cNH)     // 192 attention batches

// ---------------- scratch (device globals; no allocation allowed) ----------------
__device__ float g_col [cMP*cD];
__device__ float g_pemb[cMP*cD];
__device__ float g_pwT [cD*cD];
__device__ float g_pooled[cMP];
__device__ int   g_idx [cB*cKsel];
__device__ float g_h   [cM*cD];
__device__ float g_y   [cM*cD];
__device__ float g_qkv [cM*3*cD];
__device__ float g_q   [cBH*cS*cHD];
__device__ float g_kt  [cBH*cHD*cS];
__device__ float g_v   [cBH*cS*cHD];
__device__ float g_att [(size_t)cBH*cS*cS];
__device__ float g_o   [cBH*cS*cHD];
__device__ float g_or  [cM*cD];
__device__ float g_ffn [cM*cFF];
__device__ float g_cls [cB*cD];

// ---------------- main SGEMM: C = A(MxK) @ B(KxN) + bias [+res | gelu] ----------------
// 128x128 tile, BK=8, 256 threads, 8x8 per thread. Requires K%8==0, N%4==0.
template<int EPI>   // 0: bias; 1: bias+residual; 2: bias+gelu(exact)
__launch_bounds__(256)
__global__ void sgemm_k(const float* __restrict__ A, const float* __restrict__ Bm,
                        const float* __restrict__ bias, const float* __restrict__ res,
                        float* __restrict__ C, int M, int N, int K)
{
    __shared__ float As[8][132];
    __shared__ float Bs[8][132];
    const int bm = blockIdx.y * 128, bn = blockIdx.x * 128;
    const int tid = threadIdx.x;
    const int tx = tid & 15, ty = tid >> 4;
    const int am  = tid >> 1;            // 0..127
    const int ak  = (tid & 1) * 4;       // 0 or 4
    const int bk  = tid >> 5;            // 0..7
    const int bn4 = (tid & 31) * 4;      // 0..124

    float acc[8][8];
#pragma unroll
    for (int i = 0; i < 8; i++)
#pragma unroll
        for (int j = 0; j < 8; j++) acc[i][j] = 0.f;

    for (int k0 = 0; k0 < K; k0 += 8) {
        float4 a4 = make_float4(0.f, 0.f, 0.f, 0.f);
        if (bm + am < M)
            a4 = *reinterpret_cast<const float4*>(A + (size_t)(bm + am) * K + k0 + ak);
        As[ak+0][am] = a4.x; As[ak+1][am] = a4.y; As[ak+2][am] = a4.z; As[ak+3][am] = a4.w;

        float4 b4 = make_float4(0.f, 0.f, 0.f, 0.f);
        if (bn + bn4 < N)
            b4 = *reinterpret_cast<const float4*>(Bm + (size_t)(k0 + bk) * N + bn + bn4);
        *reinterpret_cast<float4*>(&Bs[bk][bn4]) = b4;
        __syncthreads();

#pragma unroll
        for (int kk = 0; kk < 8; kk++) {
            float a[8], b[8];
            float4 t0 = *reinterpret_cast<const float4*>(&As[kk][ty*8]);
            float4 t1 = *reinterpret_cast<const float4*>(&As[kk][ty*8+4]);
            a[0]=t0.x; a[1]=t0.y; a[2]=t0.z; a[3]=t0.w;
            a[4]=t1.x; a[5]=t1.y; a[6]=t1.z; a[7]=t1.w;
            float4 u0 = *reinterpret_cast<const float4*>(&Bs[kk][tx*8]);
            float4 u1 = *reinterpret_cast<const float4*>(&Bs[kk][tx*8+4]);
            b[0]=u0.x; b[1]=u0.y; b[2]=u0.z; b[3]=u0.w;
            b[4]=u1.x; b[5]=u1.y; b[6]=u1.z; b[7]=u1.w;
#pragma unroll
            for (int i = 0; i < 8; i++)
#pragma unroll
                for (int j = 0; j < 8; j++)
                    acc[i][j] += a[i] * b[j];
        }
        __syncthreads();
    }

#pragma unroll
    for (int i = 0; i < 8; i++) {
        int m = bm + ty*8 + i;
        if (m >= M) continue;
#pragma unroll
        for (int j = 0; j < 8; j++) {
            int n = bn + tx*8 + j;
            if (n >= N) continue;
            float v = acc[i][j] + bias[n];
            if (EPI == 1) v += res[(size_t)m * N + n];
            if (EPI == 2) v = 0.5f * v * (1.0f + erff(v * 0.70710678118654752440f));
            C[(size_t)m * N + n] = v;
        }
    }
}

// ---------------- batched GEMM (attention): C = alpha * A @ B, fully guarded ----------------
__launch_bounds__(256)
__global__ void bgemm_k(const float* __restrict__ Ag, const float* __restrict__ Bg,
                        float* __restrict__ Cg, int M, int N, int K,
                        long sA, long sB, long sC, float alpha)
{
    const float* A = Ag + (size_t)blockIdx.z * sA;
    const float* Bm = Bg + (size_t)blockIdx.z * sB;
    float* C = Cg + (size_t)blockIdx.z * sC;
    __shared__ float As[16][68];
    __shared__ float Bs[16][68];
    const int bm = blockIdx.y * 64, bn = blockIdx.x * 64;
    const int tid = threadIdx.x;
    const int tx = tid & 15, ty = tid >> 4;
    const int am = tid >> 2, ak = (tid & 3) * 4;
    const int bk = tid >> 4, bn4 = (tid & 15) * 4;
    float acc[4][4] = {};

    for (int k0 = 0; k0 < K; k0 += 16) {
#pragma unroll
        for (int c = 0; c < 4; c++) {
            int k = k0 + ak + c;
            As[ak+c][am] = (bm + am < M && k < K) ? A[(size_t)(bm+am)*K + k] : 0.f;
        }
#pragma unroll
        for (int c = 0; c < 4; c++) {
            int n = bn + bn4 + c;
            Bs[bk][bn4+c] = (k0 + bk < K && n < N) ? Bm[(size_t)(k0+bk)*N + n] : 0.f;
        }
        __syncthreads();
#pragma unroll
        for (int kk = 0; kk < 16; kk++) {
            float a[4], b[4];
#pragma unroll
            for (int i = 0; i < 4; i++) a[i] = As[kk][ty*4+i];
#pragma unroll
            for (int j = 0; j < 4; j++) b[j] = Bs[kk][tx*4+j];
#pragma unroll
            for (int i = 0; i < 4; i++)
#pragma unroll
                for (int j = 0; j < 4; j++)
                    acc[i][j] += a[i] * b[j];
        }
        __syncthreads();
    }
#pragma unroll
    for (int i = 0; i < 4; i++) {
        int m = bm + ty*4 + i;
        if (m >= M) continue;
#pragma unroll
        for (int j = 0; j < 4; j++) {
            int n = bn + tx*4 + j;
            if (n < N) C[(size_t)m*N + n] = alpha * acc[i][j];
        }
    }
}

// ---------------- small kernels ----------------
__global__ void transpose_k(const float* __restrict__ W, float* __restrict__ WT)
{   // W: (D out-major, 768 in) -> WT[k][d]
    int i = blockIdx.x * 256 + threadIdx.x;
    if (i < cD * cD) { int d = i / cD, k = i % cD; WT[k * cD + d] = W[i]; }
}

__global__ void im2col_k(const float* __restrict__ x, float* __restrict__ col)
{
    int t = blockIdx.x * 256 + threadIdx.x;
    if (t >= cMP * cD) return;
    int m = t / cD, k = t % cD;
    int b = m / cNP, p = m % cNP;
    int gy = p / cG, gx = p % cG;
    int c = k >> 8, r = k & 255;
    int py = r >> 4, px = r & 15;
    col[t] = x[(((size_t)b * cCh + c) * cHW + gy * cP + py) * cHW + gx * cP + px];
}

__global__ void pooled_k(const float* __restrict__ x, float* __restrict__ pooled)
{
    int bp = blockIdx.x;
    int b = bp / cNP, p = bp % cNP;
    int gy = p / cG, gx = p % cG;
    int t = threadIdx.x;
    int py = t >> 4, px = t & 15;
    float v = x[((size_t)b * cCh) * cHW * cHW + (size_t)(gy * cP + py) * cHW + gx * cP + px];
    __shared__ float sm[256];
    sm[t] = v; __syncthreads();
    for (int s = 128; s; s >>= 1) { if (t < s) sm[t] += sm[t + s]; __syncthreads(); }
    if (t == 0) pooled[bp] = sm[0] * (1.f / 256.f);
}

// bitonic sort 1024 (padded) by |pooled| descending; emit first K indices
__global__ void topk_k(const float* __restrict__ pooled, int* __restrict__ idx)
{
    int b = blockIdx.x;
    __shared__ float key[1024];
    __shared__ int   sid[1024];
    int t = threadIdx.x;  // 512
    for (int i = t; i < 1024; i += 512) {
        if (i < cNP) { key[i] = fabsf(pooled[b * cNP + i]); sid[i] = i; }
        else         { key[i] = -1.f; sid[i] = i; }
    }
    __syncthreads();
    for (int k = 2; k <= 1024; k <<= 1) {
        for (int j = k >> 1; j > 0; j >>= 1) {
            for (int i = t; i < 1024; i += 512) {
                int ixj = i ^ j;
                if (ixj > i) {
                    bool asc = (i & k) != 0;   // final pass: all descending
                    float ki = key[i], kj = key[ixj];
                    bool sw = asc ? (ki > kj) : (ki < kj);
                    if (sw) {
                        key[i] = kj; key[ixj] = ki;
                        int tmp = sid[i]; sid[i] = sid[ixj]; sid[ixj] = tmp;
                    }
                }
            }
            __syncthreads();
        }
    }
    for (int i = t; i < cKsel; i += 512) idx[b * cKsel + i] = sid[i];
}

__global__ void build_h_k(const float* __restrict__ pemb, const int* __restrict__ idx,
                          const float* __restrict__ cls_tok, const float* __restrict__ pos,
                          float* __restrict__ h)
{
    int row = blockIdx.x;
    int b = row / cS, s = row % cS;
    int t = threadIdx.x;
    float* hp = h + (size_t)row * cD;
    if (s == 0) {
        for (int d = t; d < cD; d += 256) hp[d] = cls_tok[d] + pos[d];
    } else {
        int p = idx[b * cKsel + s - 1];
        const float* src = pemb + (size_t)(b * cNP + p) * cD;
        const float* pp  = pos + (size_t)(1 + p) * cD;
        for (int d = t; d < cD; d += 256) hp[d] = src[d] + pp[d];
    }
}

// two-pass LayerNorm; D=768, 256 threads x 3 elems
__global__ void layernorm_k(const float* __restrict__ X, long rowStride,
                            const float* __restrict__ g, const float* __restrict__ bb,
                            float* __restrict__ Y, long outStride)
{
    int row = blockIdx.x, t = threadIdx.x;
    const float* xp = X + (size_t)row * rowStride;
    float v0 = xp[t], v1 = xp[t + 256], v2 = xp[t + 512];
    __shared__ float sm[256];
    sm[t] = v0 + v1 + v2; __syncthreads();
    for (int s = 128; s; s >>= 1) { if (t < s) sm[t] += sm[t + s]; __syncthreads(); }
    float mean = sm[0] * (1.f / 768.f); __syncthreads();
    float d0 = v0 - mean, d1 = v1 - mean, d2 = v2 - mean;
    sm[t] = d0*d0 + d1*d1 + d2*d2; __syncthreads();
    for (int s = 128; s; s >>= 1) { if (t < s) sm[t] += sm[t + s]; __syncthreads(); }
    float inv = rsqrtf(sm[0] * (1.f / 768.f) + 1e-6f);
    float* yp = Y + (size_t)row * outStride;
    yp[t]       = d0 * inv * g[t]       + bb[t];
    yp[t + 256] = d1 * inv * g[t + 256] + bb[t + 256];
    yp[t + 512] = d2 * inv * g[t + 512] + bb[t + 512];
}

__global__ void reshape_qkv_k(const float* __restrict__ qkv, float* __restrict__ q,
                              float* __restrict__ kt, float* __restrict__ v)
{
    int t = blockIdx.x * 256 + threadIdx.x;
    if (t >= cM * cD) return;
    int row = t / cD, c = t % cD;
    int b = row / cS, s = row % cS;
    int hh = c / cHD, d = c % cHD;
    size_t base = (size_t)row * (3 * cD);
    int bh = b * cNH + hh;
    q [((size_t)bh * cS + s) * cHD + d] = qkv[base + c];
    kt[((size_t)bh * cHD + d) * cS + s] = qkv[base + cD + c];
    v [((size_t)bh * cS + s) * cHD + d] = qkv[base + 2 * cD + c];
}

__global__ void reshape_o_k(const float* __restrict__ o, float* __restrict__ orr)
{
    int t = blockIdx.x * 256 + threadIdx.x;
    if (t >= cM * cD) return;
    int row = t / cD, c = t % cD;
    int b = row / cS, s = row % cS;
    int hh = c / cHD, d = c % cHD;
    orr[t] = o[(((size_t)(b * cNH + hh)) * cS + s) * cHD + d];
}

__global__ void softmax_k(float* __restrict__ att)
{
    int row = blockIdx.x;
    float* p = att + (size_t)row * cS;
    int t = threadIdx.x;
    __shared__ float sm[256];
    float v0 = (t < cS)       ? p[t]       : -3.4e38f;
    float v1 = (t + 256 < cS) ? p[t + 256] : -3.4e38f;
    sm[t] = fmaxf(v0, v1); __syncthreads();
    for (int s = 128; s; s >>= 1) { if (t < s) sm[t] = fmaxf(sm[t], sm[t + s]); __syncthreads(); }
    float mx = sm[0]; __syncthreads();
    float e0 = (t < cS)       ? expf(v0 - mx) : 0.f;
    float e1 = (t + 256 < cS) ? expf(v1 - mx) : 0.f;
    sm[t] = e0 + e1; __syncthreads();
    for (int s = 128; s; s >>= 1) { if (t < s) sm[t] += sm[t + s]; __syncthreads(); }
    float inv = 1.f / sm[0];
    if (t < cS)       p[t]       = e0 * inv;
    if (t + 256 < cS) p[t + 256] = e1 * inv;
}

// ---------------- driver ----------------
extern "C" void kernel_launch(void* const* d_in, const int* in_sizes, int n_in,
                              void* d_out, int out_size)
{
    const float* x       = (const float*)d_in[0];
    const float* patch_w = (const float*)d_in[1];
    const float* patch_b = (const float*)d_in[2];
    const float* cls_tok = (const float*)d_in[3];
    const float* pos_emb = (const float*)d_in[4];
    const float* ln1_g   = (const float*)d_in[5];
    const float* ln1_b   = (const float*)d_in[6];
    const float* Wqkv    = (const float*)d_in[7];
    const float* bqkv    = (const float*)d_in[8];
    const float* Wo      = (const float*)d_in[9];
    const float* bo      = (const float*)d_in[10];
    const float* ln2_g   = (const float*)d_in[11];
    const float* ln2_b   = (const float*)d_in[12];
    const float* W1      = (const float*)d_in[13];
    const float* b1      = (const float*)d_in[14];
    const float* W2      = (const float*)d_in[15];
    const float* b2      = (const float*)d_in[16];
    const float* lnf_g   = (const float*)d_in[17];
    const float* lnf_b   = (const float*)d_in[18];
    const float* fc_w    = (const float*)d_in[19];
    const float* fc_b    = (const float*)d_in[20];
    float* out = (float*)d_out;

    float *col, *pemb, *pwT, *pooled, *h, *y, *qkv, *q, *kt, *v, *att, *o, *orr, *ffn, *cls;
    int* idx;
    cudaGetSymbolAddress((void**)&col,    g_col);
    cudaGetSymbolAddress((void**)&pemb,   g_pemb);
    cudaGetSymbolAddress((void**)&pwT,    g_pwT);
    cudaGetSymbolAddress((void**)&pooled, g_pooled);
    cudaGetSymbolAddress((void**)&idx,    g_idx);
    cudaGetSymbolAddress((void**)&h,      g_h);
    cudaGetSymbolAddress((void**)&y,      g_y);
    cudaGetSymbolAddress((void**)&qkv,    g_qkv);
    cudaGetSymbolAddress((void**)&q,      g_q);
    cudaGetSymbolAddress((void**)&kt,     g_kt);
    cudaGetSymbolAddress((void**)&v,      g_v);
    cudaGetSymbolAddress((void**)&att,    g_att);
    cudaGetSymbolAddress((void**)&o,      g_o);
    cudaGetSymbolAddress((void**)&orr,    g_or);
    cudaGetSymbolAddress((void**)&ffn,    g_ffn);
    cudaGetSymbolAddress((void**)&cls,    g_cls);

    // patch embed
    transpose_k<<<(cD*cD + 255)/256, 256>>>(patch_w, pwT);
    im2col_k<<<(cMP*cD + 255)/256, 256>>>(x, col);
    sgemm_k<0><<<dim3(cD/128, (cMP+127)/128), 256>>>(col, pwT, patch_b, nullptr, pemb, cMP, cD, cD);

    // token selection
    pooled_k<<<cMP, 256>>>(x, pooled);
    topk_k<<<cB, 512>>>(pooled, idx);
    build_h_k<<<cM, 256>>>(pemb, idx, cls_tok, pos_emb, h);

    // transformer layers
    for (int l = 0; l < cNL; l++) {
        layernorm_k<<<cM, 256>>>(h, cD, ln1_g + (size_t)l*cD, ln1_b + (size_t)l*cD, y, cD);
        sgemm_k<0><<<dim3((3*cD)/128, (cM+127)/128), 256>>>(
            y, Wqkv + (size_t)l*cD*3*cD, bqkv + (size_t)l*3*cD, nullptr, qkv, cM, 3*cD, cD);
        reshape_qkv_k<<<(cM*cD + 255)/256, 256>>>(qkv, q, kt, v);
        bgemm_k<<<dim3((cS+63)/64, (cS+63)/64, cBH), 256>>>(
            q, kt, att, cS, cS, cHD, (long)cS*cHD, (long)cHD*cS, (long)cS*cS, 0.125f);
        softmax_k<<<cBH*cS, 256>>>(att);
        bgemm_k<<<dim3(1, (cS+63)/64, cBH), 256>>>(
            att, v, o, cS, cHD, cS, (long)cS*cS, (long)cS*cHD, (long)cS*cHD, 1.0f);
        reshape_o_k<<<(cM*cD + 255)/256, 256>>>(o, orr);
        sgemm_k<1><<<dim3(cD/128, (cM+127)/128), 256>>>(
            orr, Wo + (size_t)l*cD*cD, bo + (size_t)l*cD, h, h, cM, cD, cD);
        layernorm_k<<<cM, 256>>>(h, cD, ln2_g + (size_t)l*cD, ln2_b + (size_t)l*cD, y, cD);
        sgemm_k<2><<<dim3(cFF/128, (cM+127)/128), 256>>>(
            y, W1 + (size_t)l*cD*cFF, b1 + (size_t)l*cFF, nullptr, ffn, cM, cFF, cD);
        sgemm_k<1><<<dim3(cD/128, (cM+127)/128), 256>>>(
            ffn, W2 + (size_t)l*cFF*cD, b2 + (size_t)l*cD, h, h, cM, cD, cFF);
    }

    // head
    layernorm_k<<<cB, 256>>>(h, (long)cS*cD, lnf_g, lnf_b, cls, cD);
    sgemm_k<0><<<dim3((cNCLS+127)/128, 1), 256>>>(cls, fc_w, fc_b, nullptr, out, cB, cNCLS, cD);
}

// round 4
// speedup vs baseline: 1.0895x; 1.0895x over previous
#include <cuda_runtime.h>
#include <math.h>

// ---------------- problem constants ----------------
#define cB    16
#define cCh   3
#define cHW   384
#define cP    16
#define cG    24
#define cNP   576          // G*G
#define cD    768
#define cFF   3072
#define cNH   12
#define cNL   12
#define cKsel 288          // top-K
#define cS    289          // K+1
#define cHD   64
#define cNCLS 1000
#define cM    (cB*cS)      // 4624 rows (b,s)
#define cMP   (cB*cNP)     // 9216 patch rows
#define cBH   (cB*cNH)     // 192 attention batches

// ---------------- scratch (device globals; no allocation allowed) ----------------
__device__ float g_col [cMP*cD];
__device__ float g_pemb[cMP*cD];
__device__ float g_pwT [cD*cD];
__device__ float g_pooled[cMP];
__device__ int   g_idx [cB*cKsel];
__device__ float g_h   [cM*cD];
__device__ float g_y   [cM*cD];
__device__ float g_qkv [cM*3*cD];
__device__ float g_q   [cBH*cS*cHD];
__device__ float g_kt  [cBH*cHD*cS];
__device__ float g_v   [cBH*cS*cHD];
__device__ float g_att [(size_t)cBH*cS*cS];
__device__ float g_o   [cBH*cS*cHD];
__device__ float g_or  [cM*cD];
__device__ float g_ffn [cM*cFF];
__device__ float g_cls [cB*cD];

// ---------------- packed f32x2 helpers (Blackwell FFMA2 path) ----------------
__device__ __forceinline__ unsigned long long bcast2(float v) {
    unsigned long long r;
    asm("mov.b64 %0, {%1, %1};" : "=l"(r) : "f"(v));
    return r;
}
__device__ __forceinline__ void ffma2(unsigned long long& d, unsigned long long a,
                                      unsigned long long b) {
    asm("fma.rn.f32x2 %0, %1, %2, %0;" : "+l"(d) : "l"(a), "l"(b));
}
__device__ __forceinline__ float2 unpack2(unsigned long long v) {
    float2 f;
    asm("mov.b64 {%0, %1}, %2;" : "=f"(f.x), "=f"(f.y) : "l"(v));
    return f;
}

// ---------------- main SGEMM: C = A(MxK) @ B(KxN) + bias [+res | gelu] ----------------
// 128x128 tile, BK=8, 256 threads, 8x8 per thread via packed f32x2 FMAs.
template<int EPI>   // 0: bias; 1: bias+residual; 2: bias+gelu(exact)
__launch_bounds__(256)
__global__ void sgemm_k(const float* __restrict__ A, const float* __restrict__ Bm,
                        const float* __restrict__ bias, const float* __restrict__ res,
                        float* __restrict__ C, int M, int N, int K)
{
    __shared__ float As[8][132];
    __shared__ float Bs[8][132];
    const int bm = blockIdx.y * 128, bn = blockIdx.x * 128;
    const int tid = threadIdx.x;
    const int tx = tid & 15, ty = tid >> 4;
    const int am  = tid >> 1;            // 0..127
    const int ak  = (tid & 1) * 4;       // 0 or 4
    const int bk  = tid >> 5;            // 0..7
    const int bn4 = (tid & 31) * 4;      // 0..124

    unsigned long long acc2[8][4];       // [row i][col-pair j]
#pragma unroll
    for (int i = 0; i < 8; i++)
#pragma unroll
        for (int j = 0; j < 4; j++) acc2[i][j] = 0ull;

    for (int k0 = 0; k0 < K; k0 += 8) {
        float4 a4 = make_float4(0.f, 0.f, 0.f, 0.f);
        if (bm + am < M)
            a4 = *reinterpret_cast<const float4*>(A + (size_t)(bm + am) * K + k0 + ak);
        As[ak+0][am] = a4.x; As[ak+1][am] = a4.y; As[ak+2][am] = a4.z; As[ak+3][am] = a4.w;

        float4 b4 = make_float4(0.f, 0.f, 0.f, 0.f);
        if (bn + bn4 < N)
            b4 = *reinterpret_cast<const float4*>(Bm + (size_t)(k0 + bk) * N + bn + bn4);
        *reinterpret_cast<float4*>(&Bs[bk][bn4]) = b4;
        __syncthreads();

#pragma unroll
        for (int kk = 0; kk < 8; kk++) {
            float a[8];
            float4 t0 = *reinterpret_cast<const float4*>(&As[kk][ty*8]);
            float4 t1 = *reinterpret_cast<const float4*>(&As[kk][ty*8+4]);
            a[0]=t0.x; a[1]=t0.y; a[2]=t0.z; a[3]=t0.w;
            a[4]=t1.x; a[5]=t1.y; a[6]=t1.z; a[7]=t1.w;
            // B pairs load natively packed (16B-aligned shared rows)
            ulonglong2 bv0 = *reinterpret_cast<const ulonglong2*>(&Bs[kk][tx*8]);
            ulonglong2 bv1 = *reinterpret_cast<const ulonglong2*>(&Bs[kk][tx*8+4]);
            unsigned long long bp[4] = { bv0.x, bv0.y, bv1.x, bv1.y };
#pragma unroll
            for (int i = 0; i < 8; i++) {
                unsigned long long ab = bcast2(a[i]);
#pragma unroll
                for (int j = 0; j < 4; j++) ffma2(acc2[i][j], ab, bp[j]);
            }
        }
        __syncthreads();
    }

#pragma unroll
    for (int i = 0; i < 8; i++) {
        int m = bm + ty*8 + i;
        if (m >= M) continue;
#pragma unroll
        for (int jp = 0; jp < 4; jp++) {
            float2 f = unpack2(acc2[i][jp]);
            float vv[2] = { f.x, f.y };
#pragma unroll
            for (int q = 0; q < 2; q++) {
                int n = bn + tx*8 + jp*2 + q;
                if (n >= N) continue;
                float v = vv[q] + bias[n];
                if (EPI == 1) v += res[(size_t)m * N + n];
                if (EPI == 2) v = 0.5f * v * (1.0f + erff(v * 0.70710678118654752440f));
                C[(size_t)m * N + n] = v;
            }
        }
    }
}

// ---------------- batched GEMM (attention): C = alpha * A @ B, fully guarded ----------------
__launch_bounds__(256)
__global__ void bgemm_k(const float* __restrict__ Ag, const float* __restrict__ Bg,
                        float* __restrict__ Cg, int M, int N, int K,
                        long sA, long sB, long sC, float alpha)
{
    const float* A = Ag + (size_t)blockIdx.z * sA;
    const float* Bm = Bg + (size_t)blockIdx.z * sB;
    float* C = Cg + (size_t)blockIdx.z * sC;
    __shared__ float As[16][68];
    __shared__ float Bs[16][68];
    const int bm = blockIdx.y * 64, bn = blockIdx.x * 64;
    const int tid = threadIdx.x;
    const int tx = tid & 15, ty = tid >> 4;
    const int am = tid >> 2, ak = (tid & 3) * 4;
    const int bk = tid >> 4, bn4 = (tid & 15) * 4;
    unsigned long long acc2[4][2] = {};

    for (int k0 = 0; k0 < K; k0 += 16) {
#pragma unroll
        for (int c = 0; c < 4; c++) {
            int k = k0 + ak + c;
            As[ak+c][am] = (bm + am < M && k < K) ? A[(size_t)(bm+am)*K + k] : 0.f;
        }
#pragma unroll
        for (int c = 0; c < 4; c++) {
            int n = bn + bn4 + c;
            Bs[bk][bn4+c] = (k0 + bk < K && n < N) ? Bm[(size_t)(k0+bk)*N + n] : 0.f;
        }
        __syncthreads();
#pragma unroll
        for (int kk = 0; kk < 16; kk++) {
            ulonglong2 bv = *reinterpret_cast<const ulonglong2*>(&Bs[kk][tx*4]);
            unsigned long long bp[2] = { bv.x, bv.y };
#pragma unroll
            for (int i = 0; i < 4; i++) {
                unsigned long long ab = bcast2(As[kk][ty*4+i]);
#pragma unroll
                for (int j = 0; j < 2; j++) ffma2(acc2[i][j], ab, bp[j]);
            }
        }
        __syncthreads();
    }
#pragma unroll
    for (int i = 0; i < 4; i++) {
        int m = bm + ty*4 + i;
        if (m >= M) continue;
#pragma unroll
        for (int jp = 0; jp < 2; jp++) {
            float2 f = unpack2(acc2[i][jp]);
            int n0 = bn + tx*4 + jp*2;
            if (n0     < N) C[(size_t)m*N + n0]     = alpha * f.x;
            if (n0 + 1 < N) C[(size_t)m*N + n0 + 1] = alpha * f.y;
        }
    }
}

// ---------------- small kernels ----------------
__global__ void transpose_k(const float* __restrict__ W, float* __restrict__ WT)
{   // W: (D out-major, 768 in) -> WT[k][d]
    int i = blockIdx.x * 256 + threadIdx.x;
    if (i < cD * cD) { int d = i / cD, k = i % cD; WT[k * cD + d] = W[i]; }
}

__global__ void im2col_k(const float* __restrict__ x, float* __restrict__ col)
{
    int t = blockIdx.x * 256 + threadIdx.x;
    if (t >= cMP * cD) return;
    int m = t / cD, k = t % cD;
    int b = m / cNP, p = m % cNP;
    int gy = p / cG, gx = p % cG;
    int c = k >> 8, r = k & 255;
    int py = r >> 4, px = r & 15;
    col[t] = x[(((size_t)b * cCh + c) * cHW + gy * cP + py) * cHW + gx * cP + px];
}

__global__ void pooled_k(const float* __restrict__ x, float* __restrict__ pooled)
{
    int bp = blockIdx.x;
    int b = bp / cNP, p = bp % cNP;
    int gy = p / cG, gx = p % cG;
    int t = threadIdx.x;
    int py = t >> 4, px = t & 15;
    float v = x[((size_t)b * cCh) * cHW * cHW + (size_t)(gy * cP + py) * cHW + gx * cP + px];
    __shared__ float sm[256];
    sm[t] = v; __syncthreads();
    for (int s = 128; s; s >>= 1) { if (t < s) sm[t] += sm[t + s]; __syncthreads(); }
    if (t == 0) pooled[bp] = sm[0] * (1.f / 256.f);
}

// bitonic sort 1024 (padded) by |pooled| descending; emit first K indices
__global__ void topk_k(const float* __restrict__ pooled, int* __restrict__ idx)
{
    int b = blockIdx.x;
    __shared__ float key[1024];
    __shared__ int   sid[1024];
    int t = threadIdx.x;  // 512
    for (int i = t; i < 1024; i += 512) {
        if (i < cNP) { key[i] = fabsf(pooled[b * cNP + i]); sid[i] = i; }
        else         { key[i] = -1.f; sid[i] = i; }
    }
    __syncthreads();
    for (int k = 2; k <= 1024; k <<= 1) {
        for (int j = k >> 1; j > 0; j >>= 1) {
            for (int i = t; i < 1024; i += 512) {
                int ixj = i ^ j;
                if (ixj > i) {
                    bool asc = (i & k) != 0;   // final pass: all descending
                    float ki = key[i], kj = key[ixj];
                    bool sw = asc ? (ki > kj) : (ki < kj);
                    if (sw) {
                        key[i] = kj; key[ixj] = ki;
                        int tmp = sid[i]; sid[i] = sid[ixj]; sid[ixj] = tmp;
                    }
                }
            }
            __syncthreads();
        }
    }
    for (int i = t; i < cKsel; i += 512) idx[b * cKsel + i] = sid[i];
}

__global__ void build_h_k(const float* __restrict__ pemb, const int* __restrict__ idx,
                          const float* __restrict__ cls_tok, const float* __restrict__ pos,
                          float* __restrict__ h)
{
    int row = blockIdx.x;
    int b = row / cS, s = row % cS;
    int t = threadIdx.x;
    float* hp = h + (size_t)row * cD;
    if (s == 0) {
        for (int d = t; d < cD; d += 256) hp[d] = cls_tok[d] + pos[d];
    } else {
        int p = idx[b * cKsel + s - 1];
        const float* src = pemb + (size_t)(b * cNP + p) * cD;
        const float* pp  = pos + (size_t)(1 + p) * cD;
        for (int d = t; d < cD; d += 256) hp[d] = src[d] + pp[d];
    }
}

// two-pass LayerNorm; D=768, 256 threads x 3 elems
__global__ void layernorm_k(const float* __restrict__ X, long rowStride,
                            const float* __restrict__ g, const float* __restrict__ bb,
                            float* __restrict__ Y, long outStride)
{
    int row = blockIdx.x, t = threadIdx.x;
    const float* xp = X + (size_t)row * rowStride;
    float v0 = xp[t], v1 = xp[t + 256], v2 = xp[t + 512];
    __shared__ float sm[256];
    sm[t] = v0 + v1 + v2; __syncthreads();
    for (int s = 128; s; s >>= 1) { if (t < s) sm[t] += sm[t + s]; __syncthreads(); }
    float mean = sm[0] * (1.f / 768.f); __syncthreads();
    float d0 = v0 - mean, d1 = v1 - mean, d2 = v2 - mean;
    sm[t] = d0*d0 + d1*d1 + d2*d2; __syncthreads();
    for (int s = 128; s; s >>= 1) { if (t < s) sm[t] += sm[t + s]; __syncthreads(); }
    float inv = rsqrtf(sm[0] * (1.f / 768.f) + 1e-6f);
    float* yp = Y + (size_t)row * outStride;
    yp[t]       = d0 * inv * g[t]       + bb[t];
    yp[t + 256] = d1 * inv * g[t + 256] + bb[t + 256];
    yp[t + 512] = d2 * inv * g[t + 512] + bb[t + 512];
}

__global__ void reshape_qkv_k(const float* __restrict__ qkv, float* __restrict__ q,
                              float* __restrict__ kt, float* __restrict__ v)
{
    int t = blockIdx.x * 256 + threadIdx.x;
    if (t >= cM * cD) return;
    int row = t / cD, c = t % cD;
    int b = row / cS, s = row % cS;
    int hh = c / cHD, d = c % cHD;
    size_t base = (size_t)row * (3 * cD);
    int bh = b * cNH + hh;
    q [((size_t)bh * cS + s) * cHD + d] = qkv[base + c];
    kt[((size_t)bh * cHD + d) * cS + s] = qkv[base + cD + c];
    v [((size_t)bh * cS + s) * cHD + d] = qkv[base + 2 * cD + c];
}

__global__ void reshape_o_k(const float* __restrict__ o, float* __restrict__ orr)
{
    int t = blockIdx.x * 256 + threadIdx.x;
    if (t >= cM * cD) return;
    int row = t / cD, c = t % cD;
    int b = row / cS, s = row % cS;
    int hh = c / cHD, d = c % cHD;
    orr[t] = o[(((size_t)(b * cNH + hh)) * cS + s) * cHD + d];
}

__global__ void softmax_k(float* __restrict__ att)
{
    int row = blockIdx.x;
    float* p = att + (size_t)row * cS;
    int t = threadIdx.x;
    __shared__ float sm[256];
    float v0 = (t < cS)       ? p[t]       : -3.4e38f;
    float v1 = (t + 256 < cS) ? p[t + 256] : -3.4e38f;
    sm[t] = fmaxf(v0, v1); __syncthreads();
    for (int s = 128; s; s >>= 1) { if (t < s) sm[t] = fmaxf(sm[t], sm[t + s]); __syncthreads(); }
    float mx = sm[0]; __syncthreads();
    float e0 = (t < cS)       ? expf(v0 - mx) : 0.f;
    float e1 = (t + 256 < cS) ? expf(v1 - mx) : 0.f;
    sm[t] = e0 + e1; __syncthreads();
    for (int s = 128; s; s >>= 1) { if (t < s) sm[t] += sm[t + s]; __syncthreads(); }
    float inv = 1.f / sm[0];
    if (t < cS)       p[t]       = e0 * inv;
    if (t + 256 < cS) p[t + 256] = e1 * inv;
}

// ---------------- driver ----------------
extern "C" void kernel_launch(void* const* d_in, const int* in_sizes, int n_in,
                              void* d_out, int out_size)
{
    const float* x       = (const float*)d_in[0];
    const float* patch_w = (const float*)d_in[1];
    const float* patch_b = (const float*)d_in[2];
    const float* cls_tok = (const float*)d_in[3];
    const float* pos_emb = (const float*)d_in[4];
    const float* ln1_g   = (const float*)d_in[5];
    const float* ln1_b   = (const float*)d_in[6];
    const float* Wqkv    = (const float*)d_in[7];
    const float* bqkv    = (const float*)d_in[8];
    const float* Wo      = (const float*)d_in[9];
    const float* bo      = (const float*)d_in[10];
    const float* ln2_g   = (const float*)d_in[11];
    const float* ln2_b   = (const float*)d_in[12];
    const float* W1      = (const float*)d_in[13];
    const float* b1      = (const float*)d_in[14];
    const float* W2      = (const float*)d_in[15];
    const float* b2      = (const float*)d_in[16];
    const float* lnf_g   = (const float*)d_in[17];
    const float* lnf_b   = (const float*)d_in[18];
    const float* fc_w    = (const float*)d_in[19];
    const float* fc_b    = (const float*)d_in[20];
    float* out = (float*)d_out;

    float *col, *pemb, *pwT, *pooled, *h, *y, *qkv, *q, *kt, *v, *att, *o, *orr, *ffn, *cls;
    int* idx;
    cudaGetSymbolAddress((void**)&col,    g_col);
    cudaGetSymbolAddress((void**)&pemb,   g_pemb);
    cudaGetSymbolAddress((void**)&pwT,    g_pwT);
    cudaGetSymbolAddress((void**)&pooled, g_pooled);
    cudaGetSymbolAddress((void**)&idx,    g_idx);
    cudaGetSymbolAddress((void**)&h,      g_h);
    cudaGetSymbolAddress((void**)&y,      g_y);
    cudaGetSymbolAddress((void**)&qkv,    g_qkv);
    cudaGetSymbolAddress((void**)&q,      g_q);
    cudaGetSymbolAddress((void**)&kt,     g_kt);
    cudaGetSymbolAddress((void**)&v,      g_v);
    cudaGetSymbolAddress((void**)&att,    g_att);
    cudaGetSymbolAddress((void**)&o,      g_o);
    cudaGetSymbolAddress((void**)&orr,    g_or);
    cudaGetSymbolAddress((void**)&ffn,    g_ffn);
    cudaGetSymbolAddress((void**)&cls,    g_cls);

    // patch embed
    transpose_k<<<(cD*cD + 255)/256, 256>>>(patch_w, pwT);
    im2col_k<<<(cMP*cD + 255)/256, 256>>>(x, col);
    sgemm_k<0><<<dim3(cD/128, (cMP+127)/128), 256>>>(col, pwT, patch_b, nullptr, pemb, cMP, cD, cD);

    // token selection
    pooled_k<<<cMP, 256>>>(x, pooled);
    topk_k<<<cB, 512>>>(pooled, idx);
    build_h_k<<<cM, 256>>>(pemb, idx, cls_tok, pos_emb, h);

    // transformer layers
    for (int l = 0; l < cNL; l++) {
        layernorm_k<<<cM, 256>>>(h, cD, ln1_g + (size_t)l*cD, ln1_b + (size_t)l*cD, y, cD);
        sgemm_k<0><<<dim3((3*cD)/128, (cM+127)/128), 256>>>(
            y, Wqkv + (size_t)l*cD*3*cD, bqkv + (size_t)l*3*cD, nullptr, qkv, cM, 3*cD, cD);
        reshape_qkv_k<<<(cM*cD + 255)/256, 256>>>(qkv, q, kt, v);
        bgemm_k<<<dim3((cS+63)/64, (cS+63)/64, cBH), 256>>>(
            q, kt, att, cS, cS, cHD, (long)cS*cHD, (long)cHD*cS, (long)cS*cS, 0.125f);
        softmax_k<<<cBH*cS, 256>>>(att);
        bgemm_k<<<dim3(1, (cS+63)/64, cBH), 256>>>(
            att, v, o, cS, cHD, cS, (long)cS*cS, (long)cS*cHD, (long)cS*cHD, 1.0f);
        reshape_o_k<<<(cM*cD + 255)/256, 256>>>(o, orr);
        sgemm_k<1><<<dim3(cD/128, (cM+127)/128), 256>>>(
            orr, Wo + (size_t)l*cD*cD, bo + (size_t)l*cD, h, h, cM, cD, cD);
        layernorm_k<<<cM, 256>>>(h, cD, ln2_g + (size_t)l*cD, ln2_b + (size_t)l*cD, y, cD);
        sgemm_k<2><<<dim3(cFF/128, (cM+127)/128), 256>>>(
            y, W1 + (size_t)l*cD*cFF, b1 + (size_t)l*cFF, nullptr, ffn, cM, cFF, cD);
        sgemm_k<1><<<dim3(cD/128, (cM+127)/128), 256>>>(
            ffn, W2 + (size_t)l*cFF*cD, b2 + (size_t)l*cD, h, h, cM, cD, cFF);
    }

    // head
    layernorm_k<<<cB, 256>>>(h, (long)cS*cD, lnf_g, lnf_b, cls, cD);
    sgemm_k<0><<<dim3((cNCLS+127)/128, 1), 256>>>(cls, fc_w, fc_b, nullptr, out, cB, cNCLS, cD);
}

// round 9
// speedup vs baseline: 1.5989x; 1.4676x over previous
#include <cuda_runtime.h>
#include <cuda_bf16.h>
#include <math.h>

// ---------------- problem constants ----------------
#define cB    16
#define cCh   3
#define cHW   384
#define cP    16
#define cG    24
#define cNP   576          // G*G
#define cD    768
#define cFF   3072
#define cNH   12
#define cNL   12
#define cKsel 288          // top-K
#define cS    289          // K+1
#define cHD   64
#define cNCLS 1000
#define cM    (cB*cS)      // 4624 rows (b,s)
#define cMP   (cB*cNP)     // 9216 patch rows
#define cBH   (cB*cNH)     // 192 attention batches

// ---------------- scratch (device globals; no allocation allowed) ----------------
__device__ float g_col [cMP*cD];
__device__ float g_pemb[cMP*cD];
__device__ float g_pooled[cMP];
__device__ int   g_idx [cB*cKsel];
__device__ float g_h   [cM*cD];
__device__ float g_y   [cM*cD];
__device__ float g_qkv [cM*3*cD];
__device__ float g_q   [cBH*cS*cHD];
__device__ float g_kt  [cBH*cHD*cS];
__device__ float g_v   [cBH*cS*cHD];
__device__ float g_att [(size_t)cBH*cS*cS];
__device__ float g_o   [cBH*cS*cHD];
__device__ float g_or  [cM*cD];
__device__ float g_ffn [cM*cFF];
__device__ float g_cls [cB*cD];
// bf16 split buffers (16B-aligned for uint4 loads). 3-term split: 3x columns.
// activations: max rows=cMP(9216) x 3*cD, and cM(4624) x 3*cFF(9216) = 42.6M elems
__device__ __align__(16) __nv_bfloat16 g_abf[(size_t)cM*3*cFF];
// weights K-major [N][3K], max 3072x2304 = 768x9216 = 7.08M elems
__device__ __align__(16) __nv_bfloat16 g_wt [(size_t)cFF*3*cD];

// ---------------- 3-term split conversions ----------------
// Activation split: fp32 X[R][C] -> bf16 Y[R][3C] = [hi | lo | hi]
__global__ void split_rows_a_k(const float* __restrict__ X, __nv_bfloat16* __restrict__ Y,
                               int R, int C)
{
    int i = blockIdx.x * 256 + threadIdx.x;
    if (i >= R * C) return;
    int r = i / C, c = i % C;
    float x = X[i];
    __nv_bfloat16 hi = __float2bfloat16(x);
    __nv_bfloat16 lo = __float2bfloat16(x - __bfloat162float(hi));
    size_t base = (size_t)r * (3 * C);
    Y[base + c]         = hi;
    Y[base + C + c]     = lo;
    Y[base + 2 * C + c] = hi;
}

// Weight split (already K-major [N][K]): fp32 W[N][K] -> bf16 Y[N][3K] = [hi | hi | lo]
__global__ void split_rows_w_k(const float* __restrict__ W, __nv_bfloat16* __restrict__ Y,
                               int N, int K)
{
    int i = blockIdx.x * 256 + threadIdx.x;
    if (i >= N * K) return;
    int n = i / K, k = i % K;
    float x = W[i];
    __nv_bfloat16 hi = __float2bfloat16(x);
    __nv_bfloat16 lo = __float2bfloat16(x - __bfloat162float(hi));
    size_t base = (size_t)n * (3 * K);
    Y[base + k]         = hi;
    Y[base + K + k]     = hi;
    Y[base + 2 * K + k] = lo;
}

// Weight transpose+split: fp32 W[K][N] -> bf16 Bt[N][3K] = [hi | hi | lo]
__global__ void split_transpose_k(const float* __restrict__ W, __nv_bfloat16* __restrict__ Bt,
                                  int K, int N)
{
    __shared__ float sm[32][33];
    int k0 = blockIdx.y * 32, n0 = blockIdx.x * 32;
    int tx = threadIdx.x, ty = threadIdx.y;   // 32 x 8
#pragma unroll
    for (int i = 0; i < 4; i++) {
        int k = k0 + ty + i * 8, n = n0 + tx;
        sm[ty + i * 8][tx] = (k < K && n < N) ? W[(size_t)k * N + n] : 0.f;
    }
    __syncthreads();
#pragma unroll
    for (int i = 0; i < 4; i++) {
        int n = n0 + ty + i * 8, k = k0 + tx;
        if (n < N && k < K) {
            float v = sm[tx][ty + i * 8];
            __nv_bfloat16 hi = __float2bfloat16(v);
            __nv_bfloat16 lo = __float2bfloat16(v - __bfloat162float(hi));
            size_t base = (size_t)n * (3 * K);
            Bt[base + k]         = hi;
            Bt[base + K + k]     = hi;
            Bt[base + 2 * K + k] = lo;
        }
    }
}

// ---------------- tensor-core GEMM: C(MxN) = A[M][K3] @ Bt[N][K3]^T + epilogue ----------------
// Both operands bf16 K-major. 128x128 block, 8 warps (2x4) of 64x32, BK=32.
// mma.sync.aligned.m16n8k16.row.col.f32.bf16.bf16.f32
#define TSTR 40   // smem row stride (bf16 elems)
template<int EPI>   // 0: bias; 1: bias+residual; 2: bias+gelu(exact)
__launch_bounds__(256)
__global__ void tgemm_k(const __nv_bfloat16* __restrict__ A, const __nv_bfloat16* __restrict__ Bt,
                        const float* __restrict__ bias, const float* __restrict__ res,
                        float* __restrict__ C, int M, int N, int K2)
{
    __shared__ __nv_bfloat16 As[128 * TSTR];
    __shared__ __nv_bfloat16 Bs[128 * TSTR];
    const int bm = blockIdx.y * 128, bn = blockIdx.x * 128;
    const int tid = threadIdx.x;
    const int w = tid >> 5, lane = tid & 31;
    const int wm = (w >> 2) * 64, wn = (w & 3) * 32;
    const int grp = lane >> 2, tig = lane & 3;

    float acc[4][4][4];
#pragma unroll
    for (int mi = 0; mi < 4; mi++)
#pragma unroll
        for (int nj = 0; nj < 4; nj++)
#pragma unroll
            for (int r = 0; r < 4; r++) acc[mi][nj][r] = 0.f;

    const uint4 z4 = make_uint4(0u, 0u, 0u, 0u);
    for (int k0 = 0; k0 < K2; k0 += 32) {
#pragma unroll
        for (int it = 0; it < 2; it++) {
            int li = it * 256 + tid;
            int row = li >> 2, seg = li & 3;
            uint4 va = z4;
            if (bm + row < M)
                va = *reinterpret_cast<const uint4*>(A + (size_t)(bm + row) * K2 + k0 + seg * 8);
            *reinterpret_cast<uint4*>(As + row * TSTR + seg * 8) = va;
            uint4 vb = z4;
            if (bn + row < N)
                vb = *reinterpret_cast<const uint4*>(Bt + (size_t)(bn + row) * K2 + k0 + seg * 8);
            *reinterpret_cast<uint4*>(Bs + row * TSTR + seg * 8) = vb;
        }
        __syncthreads();

#pragma unroll
        for (int ks = 0; ks < 2; ks++) {
            const int kb = ks * 16;
            unsigned afr[4][4], bfr[4][2];
#pragma unroll
            for (int mi = 0; mi < 4; mi++) {
                const __nv_bfloat16* ap = As + (wm + mi * 16 + grp) * TSTR + kb + tig * 2;
                afr[mi][0] = *reinterpret_cast<const unsigned*>(ap);
                afr[mi][1] = *reinterpret_cast<const unsigned*>(ap + 8 * TSTR);
                afr[mi][2] = *reinterpret_cast<const unsigned*>(ap + 8);
                afr[mi][3] = *reinterpret_cast<const unsigned*>(ap + 8 * TSTR + 8);
            }
#pragma unroll
            for (int nj = 0; nj < 4; nj++) {
                const __nv_bfloat16* bp = Bs + (wn + nj * 8 + grp) * TSTR + kb + tig * 2;
                bfr[nj][0] = *reinterpret_cast<const unsigned*>(bp);
                bfr[nj][1] = *reinterpret_cast<const unsigned*>(bp + 8);
            }
#pragma unroll
            for (int mi = 0; mi < 4; mi++)
#pragma unroll
                for (int nj = 0; nj < 4; nj++) {
                    asm volatile(
                        "mma.sync.aligned.m16n8k16.row.col.f32.bf16.bf16.f32 "
                        "{%0,%1,%2,%3}, {%4,%5,%6,%7}, {%8,%9}, {%0,%1,%2,%3};"
                        : "+f"(acc[mi][nj][0]), "+f"(acc[mi][nj][1]),
                          "+f"(acc[mi][nj][2]), "+f"(acc[mi][nj][3])
                        : "r"(afr[mi][0]), "r"(afr[mi][1]), "r"(afr[mi][2]), "r"(afr[mi][3]),
                          "r"(bfr[nj][0]), "r"(bfr[nj][1]));
                }
        }
        __syncthreads();
    }

    // epilogue: c0,c1 -> (row, col), (row, col+1); c2,c3 -> (row+8, col), (row+8, col+1)
#pragma unroll
    for (int mi = 0; mi < 4; mi++) {
#pragma unroll
        for (int nj = 0; nj < 4; nj++) {
            int row0 = bm + wm + mi * 16 + grp;
            int col0 = bn + wn + nj * 8 + tig * 2;
#pragma unroll
            for (int half = 0; half < 2; half++) {
                int row = row0 + half * 8;
                if (row >= M) continue;
#pragma unroll
                for (int qq = 0; qq < 2; qq++) {
                    int col = col0 + qq;
                    if (col >= N) continue;
                    float v = acc[mi][nj][half * 2 + qq] + bias[col];
                    if (EPI == 1) v += res[(size_t)row * N + col];
                    if (EPI == 2) v = 0.5f * v * (1.0f + erff(v * 0.70710678118654752440f));
                    C[(size_t)row * N + col] = v;
                }
            }
        }
    }
}

// ---------------- scalar fp32 GEMM (head only) ----------------
template<int EPI>
__launch_bounds__(256)
__global__ void sgemm_k(const float* __restrict__ A, const float* __restrict__ Bm,
                        const float* __restrict__ bias, const float* __restrict__ res,
                        float* __restrict__ C, int M, int N, int K)
{
    __shared__ float As[8][132];
    __shared__ float Bs[8][132];
    const int bm = blockIdx.y * 128, bn = blockIdx.x * 128;
    const int tid = threadIdx.x;
    const int tx = tid & 15, ty = tid >> 4;
    const int am  = tid >> 1;
    const int ak  = (tid & 1) * 4;
    const int bk  = tid >> 5;
    const int bn4 = (tid & 31) * 4;

    float acc[8][8];
#pragma unroll
    for (int i = 0; i < 8; i++)
#pragma unroll
        for (int j = 0; j < 8; j++) acc[i][j] = 0.f;

    for (int k0 = 0; k0 < K; k0 += 8) {
        float4 a4 = make_float4(0.f, 0.f, 0.f, 0.f);
        if (bm + am < M)
            a4 = *reinterpret_cast<const float4*>(A + (size_t)(bm + am) * K + k0 + ak);
        As[ak+0][am] = a4.x; As[ak+1][am] = a4.y; As[ak+2][am] = a4.z; As[ak+3][am] = a4.w;

        float4 b4 = make_float4(0.f, 0.f, 0.f, 0.f);
        if (bn + bn4 < N)
            b4 = *reinterpret_cast<const float4*>(Bm + (size_t)(k0 + bk) * N + bn + bn4);
        *reinterpret_cast<float4*>(&Bs[bk][bn4]) = b4;
        __syncthreads();

#pragma unroll
        for (int kk = 0; kk < 8; kk++) {
            float a[8], b[8];
            float4 t0 = *reinterpret_cast<const float4*>(&As[kk][ty*8]);
            float4 t1 = *reinterpret_cast<const float4*>(&As[kk][ty*8+4]);
            a[0]=t0.x; a[1]=t0.y; a[2]=t0.z; a[3]=t0.w;
            a[4]=t1.x; a[5]=t1.y; a[6]=t1.z; a[7]=t1.w;
            float4 u0 = *reinterpret_cast<const float4*>(&Bs[kk][tx*8]);
            float4 u1 = *reinterpret_cast<const float4*>(&Bs[kk][tx*8+4]);
            b[0]=u0.x; b[1]=u0.y; b[2]=u0.z; b[3]=u0.w;
            b[4]=u1.x; b[5]=u1.y; b[6]=u1.z; b[7]=u1.w;
#pragma unroll
            for (int i = 0; i < 8; i++)
#pragma unroll
                for (int j = 0; j < 8; j++)
                    acc[i][j] += a[i] * b[j];
        }
        __syncthreads();
    }

#pragma unroll
    for (int i = 0; i < 8; i++) {
        int m = bm + ty*8 + i;
        if (m >= M) continue;
#pragma unroll
        for (int j = 0; j < 8; j++) {
            int n = bn + tx*8 + j;
            if (n >= N) continue;
            float v = acc[i][j] + bias[n];
            if (EPI == 1) v += res[(size_t)m * N + n];
            if (EPI == 2) v = 0.5f * v * (1.0f + erff(v * 0.70710678118654752440f));
            C[(size_t)m * N + n] = v;
        }
    }
}

// ---------------- batched GEMM (attention) ----------------
__launch_bounds__(256)
__global__ void bgemm_k(const float* __restrict__ Ag, const float* __restrict__ Bg,
                        float* __restrict__ Cg, int M, int N, int K,
                        long sA, long sB, long sC, float alpha)
{
    const float* A = Ag + (size_t)blockIdx.z * sA;
    const float* Bm = Bg + (size_t)blockIdx.z * sB;
    float* C = Cg + (size_t)blockIdx.z * sC;
    __shared__ float As[16][68];
    __shared__ float Bs[16][68];
    const int bm = blockIdx.y * 64, bn = blockIdx.x * 64;
    const int tid = threadIdx.x;
    const int tx = tid & 15, ty = tid >> 4;
    const int am = tid >> 2, ak = (tid & 3) * 4;
    const int bk = tid >> 4, bn4 = (tid & 15) * 4;
    float acc[4][4] = {};

    for (int k0 = 0; k0 < K; k0 += 16) {
#pragma unroll
        for (int c = 0; c < 4; c++) {
            int k = k0 + ak + c;
            As[ak+c][am] = (bm + am < M && k < K) ? A[(size_t)(bm+am)*K + k] : 0.f;
        }
#pragma unroll
        for (int c = 0; c < 4; c++) {
            int n = bn + bn4 + c;
            Bs[bk][bn4+c] = (k0 + bk < K && n < N) ? Bm[(size_t)(k0+bk)*N + n] : 0.f;
        }
        __syncthreads();
#pragma unroll
        for (int kk = 0; kk < 16; kk++) {
            float a[4], b[4];
#pragma unroll
            for (int i = 0; i < 4; i++) a[i] = As[kk][ty*4+i];
#pragma unroll
            for (int j = 0; j < 4; j++) b[j] = Bs[kk][tx*4+j];
#pragma unroll
            for (int i = 0; i < 4; i++)
#pragma unroll
                for (int j = 0; j < 4; j++)
                    acc[i][j] += a[i] * b[j];
        }
        __syncthreads();
    }
#pragma unroll
    for (int i = 0; i < 4; i++) {
        int m = bm + ty*4 + i;
        if (m >= M) continue;
#pragma unroll
        for (int j = 0; j < 4; j++) {
            int n = bn + tx*4 + j;
            if (n < N) C[(size_t)m*N + n] = alpha * acc[i][j];
        }
    }
}

// ---------------- small kernels ----------------
__global__ void im2col_k(const float* __restrict__ x, float* __restrict__ col)
{
    int t = blockIdx.x * 256 + threadIdx.x;
    if (t >= cMP * cD) return;
    int m = t / cD, k = t % cD;
    int b = m / cNP, p = m % cNP;
    int gy = p / cG, gx = p % cG;
    int c = k >> 8, r = k & 255;
    int py = r >> 4, px = r & 15;
    col[t] = x[(((size_t)b * cCh + c) * cHW + gy * cP + py) * cHW + gx * cP + px];
}

__global__ void pooled_k(const float* __restrict__ x, float* __restrict__ pooled)
{
    int bp = blockIdx.x;
    int b = bp / cNP, p = bp % cNP;
    int gy = p / cG, gx = p % cG;
    int t = threadIdx.x;
    int py = t >> 4, px = t & 15;
    float v = x[((size_t)b * cCh) * cHW * cHW + (size_t)(gy * cP + py) * cHW + gx * cP + px];
    __shared__ float sm[256];
    sm[t] = v; __syncthreads();
    for (int s = 128; s; s >>= 1) { if (t < s) sm[t] += sm[t + s]; __syncthreads(); }
    if (t == 0) pooled[bp] = sm[0] * (1.f / 256.f);
}

__global__ void topk_k(const float* __restrict__ pooled, int* __restrict__ idx)
{
    int b = blockIdx.x;
    __shared__ float key[1024];
    __shared__ int   sid[1024];
    int t = threadIdx.x;  // 512
    for (int i = t; i < 1024; i += 512) {
        if (i < cNP) { key[i] = fabsf(pooled[b * cNP + i]); sid[i] = i; }
        else         { key[i] = -1.f; sid[i] = i; }
    }
    __syncthreads();
    for (int k = 2; k <= 1024; k <<= 1) {
        for (int j = k >> 1; j > 0; j >>= 1) {
            for (int i = t; i < 1024; i += 512) {
                int ixj = i ^ j;
                if (ixj > i) {
                    bool asc = (i & k) != 0;
                    float ki = key[i], kj = key[ixj];
                    bool sw = asc ? (ki > kj) : (ki < kj);
                    if (sw) {
                        key[i] = kj; key[ixj] = ki;
                        int tmp = sid[i]; sid[i] = sid[ixj]; sid[ixj] = tmp;
                    }
                }
            }
            __syncthreads();
        }
    }
    for (int i = t; i < cKsel; i += 512) idx[b * cKsel + i] = sid[i];
}

__global__ void build_h_k(const float* __restrict__ pemb, const int* __restrict__ idx,
                          const float* __restrict__ cls_tok, const float* __restrict__ pos,
                          float* __restrict__ h)
{
    int row = blockIdx.x;
    int b = row / cS, s = row % cS;
    int t = threadIdx.x;
    float* hp = h + (size_t)row * cD;
    if (s == 0) {
        for (int d = t; d < cD; d += 256) hp[d] = cls_tok[d] + pos[d];
    } else {
        int p = idx[b * cKsel + s - 1];
        const float* src = pemb + (size_t)(b * cNP + p) * cD;
        const float* pp  = pos + (size_t)(1 + p) * cD;
        for (int d = t; d < cD; d += 256) hp[d] = src[d] + pp[d];
    }
}

__global__ void layernorm_k(const float* __restrict__ X, long rowStride,
                            const float* __restrict__ g, const float* __restrict__ bb,
                            float* __restrict__ Y, long outStride)
{
    int row = blockIdx.x, t = threadIdx.x;
    const float* xp = X + (size_t)row * rowStride;
    float v0 = xp[t], v1 = xp[t + 256], v2 = xp[t + 512];
    __shared__ float sm[256];
    sm[t] = v0 + v1 + v2; __syncthreads();
    for (int s = 128; s; s >>= 1) { if (t < s) sm[t] += sm[t + s]; __syncthreads(); }
    float mean = sm[0] * (1.f / 768.f); __syncthreads();
    float d0 = v0 - mean, d1 = v1 - mean, d2 = v2 - mean;
    sm[t] = d0*d0 + d1*d1 + d2*d2; __syncthreads();
    for (int s = 128; s; s >>= 1) { if (t < s) sm[t] += sm[t + s]; __syncthreads(); }
    float inv = rsqrtf(sm[0] * (1.f / 768.f) + 1e-6f);
    float* yp = Y + (size_t)row * outStride;
    yp[t]       = d0 * inv * g[t]       + bb[t];
    yp[t + 256] = d1 * inv * g[t + 256] + bb[t + 256];
    yp[t + 512] = d2 * inv * g[t + 512] + bb[t + 512];
}

__global__ void reshape_qkv_k(const float* __restrict__ qkv, float* __restrict__ q,
                              float* __restrict__ kt, float* __restrict__ v)
{
    int t = blockIdx.x * 256 + threadIdx.x;
    if (t >= cM * cD) return;
    int row = t / cD, c = t % cD;
    int b = row / cS, s = row % cS;
    int hh = c / cHD, d = c % cHD;
    size_t base = (size_t)row * (3 * cD);
    int bh = b * cNH + hh;
    q [((size_t)bh * cS + s) * cHD + d] = qkv[base + c];
    kt[((size_t)bh * cHD + d) * cS + s] = qkv[base + cD + c];
    v [((size_t)bh * cS + s) * cHD + d] = qkv[base + 2 * cD + c];
}

__global__ void reshape_o_k(const float* __restrict__ o, float* __restrict__ orr)
{
    int t = blockIdx.x * 256 + threadIdx.x;
    if (t >= cM * cD) return;
    int row = t / cD, c = t % cD;
    int b = row / cS, s = row % cS;
    int hh = c / cHD, d = c % cHD;
    orr[t] = o[(((size_t)(b * cNH + hh)) * cS + s) * cHD + d];
}

__global__ void softmax_k(float* __restrict__ att)
{
    int row = blockIdx.x;
    float* p = att + (size_t)row * cS;
    int t = threadIdx.x;
    __shared__ float sm[256];
    float v0 = (t < cS)       ? p[t]       : -3.4e38f;
    float v1 = (t + 256 < cS) ? p[t + 256] : -3.4e38f;
    sm[t] = fmaxf(v0, v1); __syncthreads();
    for (int s = 128; s; s >>= 1) { if (t < s) sm[t] = fmaxf(sm[t], sm[t + s]); __syncthreads(); }
    float mx = sm[0]; __syncthreads();
    float e0 = (t < cS)       ? expf(v0 - mx) : 0.f;
    float e1 = (t + 256 < cS) ? expf(v1 - mx) : 0.f;
    sm[t] = e0 + e1; __syncthreads();
    for (int s = 128; s; s >>= 1) { if (t < s) sm[t] += sm[t + s]; __syncthreads(); }
    float inv = 1.f / sm[0];
    if (t < cS)       p[t]       = e0 * inv;
    if (t + 256 < cS) p[t + 256] = e1 * inv;
}

// ---------------- driver ----------------
static inline dim3 tgrid(int M, int N) { return dim3((N + 127) / 128, (M + 127) / 128); }

extern "C" void kernel_launch(void* const* d_in, const int* in_sizes, int n_in,
                              void* d_out, int out_size)
{
    const float* x       = (const float*)d_in[0];
    const float* patch_w = (const float*)d_in[1];
    const float* patch_b = (const float*)d_in[2];
    const float* cls_tok = (const float*)d_in[3];
    const float* pos_emb = (const float*)d_in[4];
    const float* ln1_g   = (const float*)d_in[5];
    const float* ln1_b   = (const float*)d_in[6];
    const float* Wqkv    = (const float*)d_in[7];
    const float* bqkv    = (const float*)d_in[8];
    const float* Wo      = (const float*)d_in[9];
    const float* bo      = (const float*)d_in[10];
    const float* ln2_g   = (const float*)d_in[11];
    const float* ln2_b   = (const float*)d_in[12];
    const float* W1      = (const float*)d_in[13];
    const float* b1      = (const float*)d_in[14];
    const float* W2      = (const float*)d_in[15];
    const float* b2      = (const float*)d_in[16];
    const float* lnf_g   = (const float*)d_in[17];
    const float* lnf_b   = (const float*)d_in[18];
    const float* fc_w    = (const float*)d_in[19];
    const float* fc_b    = (const float*)d_in[20];
    float* out = (float*)d_out;

    float *col, *pemb, *pooled, *h, *y, *qkv, *q, *kt, *v, *att, *o, *orr, *ffn, *cls;
    __nv_bfloat16 *abf, *wt;
    int* idx;
    cudaGetSymbolAddress((void**)&col,    g_col);
    cudaGetSymbolAddress((void**)&pemb,   g_pemb);
    cudaGetSymbolAddress((void**)&pooled, g_pooled);
    cudaGetSymbolAddress((void**)&idx,    g_idx);
    cudaGetSymbolAddress((void**)&h,      g_h);
    cudaGetSymbolAddress((void**)&y,      g_y);
    cudaGetSymbolAddress((void**)&qkv,    g_qkv);
    cudaGetSymbolAddress((void**)&q,      g_q);
    cudaGetSymbolAddress((void**)&kt,     g_kt);
    cudaGetSymbolAddress((void**)&v,      g_v);
    cudaGetSymbolAddress((void**)&att,    g_att);
    cudaGetSymbolAddress((void**)&o,      g_o);
    cudaGetSymbolAddress((void**)&orr,    g_or);
    cudaGetSymbolAddress((void**)&ffn,    g_ffn);
    cudaGetSymbolAddress((void**)&cls,    g_cls);
    cudaGetSymbolAddress((void**)&abf,    g_abf);
    cudaGetSymbolAddress((void**)&wt,     g_wt);

    const dim3 tt(32, 8);

    // patch embed: col[9216][768] @ patch_w^T  (patch_w is [768 out][768 in] = [N][K] already)
    im2col_k<<<(cMP*cD + 255)/256, 256>>>(x, col);
    split_rows_a_k<<<(cMP*cD + 255)/256, 256>>>(col, abf, cMP, cD);
    split_rows_w_k<<<(cD*cD + 255)/256, 256>>>(patch_w, wt, cD, cD);
    tgemm_k<0><<<tgrid(cMP, cD), 256>>>(abf, wt, patch_b, nullptr, pemb, cMP, cD, 3*cD);

    // token selection
    pooled_k<<<cMP, 256>>>(x, pooled);
    topk_k<<<cB, 512>>>(pooled, idx);
    build_h_k<<<cM, 256>>>(pemb, idx, cls_tok, pos_emb, h);

    // transformer layers
    for (int l = 0; l < cNL; l++) {
        layernorm_k<<<cM, 256>>>(h, cD, ln1_g + (size_t)l*cD, ln1_b + (size_t)l*cD, y, cD);
        split_rows_a_k<<<(cM*cD + 255)/256, 256>>>(y, abf, cM, cD);
        split_transpose_k<<<dim3((3*cD+31)/32, (cD+31)/32), tt>>>(Wqkv + (size_t)l*cD*3*cD, wt, cD, 3*cD);
        tgemm_k<0><<<tgrid(cM, 3*cD), 256>>>(abf, wt, bqkv + (size_t)l*3*cD, nullptr, qkv, cM, 3*cD, 3*cD);

        reshape_qkv_k<<<(cM*cD + 255)/256, 256>>>(qkv, q, kt, v);
        bgemm_k<<<dim3((cS+63)/64, (cS+63)/64, cBH), 256>>>(
            q, kt, att, cS, cS, cHD, (long)cS*cHD, (long)cHD*cS, (long)cS*cS, 0.125f);
        softmax_k<<<cBH*cS, 256>>>(att);
        bgemm_k<<<dim3(1, (cS+63)/64, cBH), 256>>>(
            att, v, o, cS, cHD, cS, (long)cS*cS, (long)cS*cHD, (long)cS*cHD, 1.0f);
        reshape_o_k<<<(cM*cD + 255)/256, 256>>>(o, orr);

        split_rows_a_k<<<(cM*cD + 255)/256, 256>>>(orr, abf, cM, cD);
        split_transpose_k<<<dim3((cD+31)/32, (cD+31)/32), tt>>>(Wo + (size_t)l*cD*cD, wt, cD, cD);
        tgemm_k<1><<<tgrid(cM, cD), 256>>>(abf, wt, bo + (size_t)l*cD, h, h, cM, cD, 3*cD);

        layernorm_k<<<cM, 256>>>(h, cD, ln2_g + (size_t)l*cD, ln2_b + (size_t)l*cD, y, cD);
        split_rows_a_k<<<(cM*cD + 255)/256, 256>>>(y, abf, cM, cD);
        split_transpose_k<<<dim3((cFF+31)/32, (cD+31)/32), tt>>>(W1 + (size_t)l*cD*cFF, wt, cD, cFF);
        tgemm_k<2><<<tgrid(cM, cFF), 256>>>(abf, wt, b1 + (size_t)l*cFF, nullptr, ffn, cM, cFF, 3*cD);

        split_rows_a_k<<<(cM*cFF + 255)/256, 256>>>(ffn, abf, cM, cFF);
        split_transpose_k<<<dim3((cD+31)/32, (cFF+31)/32), tt>>>(W2 + (size_t)l*cFF*cD, wt, cFF, cD);
        tgemm_k<1><<<tgrid(cM, cD), 256>>>(abf, wt, b2 + (size_t)l*cD, h, h, cM, cD, 3*cFF);
    }

    // head (tiny — scalar fp32)
    layernorm_k<<<cB, 256>>>(h, (long)cS*cD, lnf_g, lnf_b, cls, cD);
    sgemm_k<0><<<dim3((cNCLS+127)/128, 1), 256>>>(cls, fc_w, fc_b, nullptr, out, cB, cNCLS, cD);
}

// round 10
// speedup vs baseline: 1.7234x; 1.0779x over previous
#include <cuda_runtime.h>
#include <cuda_bf16.h>
#include <math.h>

// ---------------- problem constants ----------------
#define cB    16
#define cCh   3
#define cHW   384
#define cP    16
#define cG    24
#define cNP   576          // G*G
#define cD    768
#define cFF   3072
#define cNH   12
#define cNL   12
#define cKsel 288          // top-K
#define cS    289          // K+1
#define cHD   64
#define cNCLS 1000
#define cM    (cB*cS)      // 4624 rows (b,s)
#define cMP   (cB*cNP)     // 9216 patch rows
#define cBH   (cB*cNH)     // 192 attention batches

// ---------------- scratch (device globals; no allocation allowed) ----------------
__device__ float g_col [cMP*cD];
__device__ float g_pemb[cMP*cD];
__device__ float g_pooled[cMP];
__device__ int   g_idx [cB*cKsel];
__device__ float g_h   [cM*cD];
__device__ float g_y   [cM*cD];
__device__ float g_qkv [cM*3*cD];
__device__ float g_q   [cBH*cS*cHD];
__device__ float g_kt  [cBH*cHD*cS];
__device__ float g_v   [cBH*cS*cHD];
__device__ float g_att [(size_t)cBH*cS*cS];
__device__ float g_o   [cBH*cS*cHD];
__device__ float g_or  [cM*cD];
__device__ float g_ffn [cM*cFF];
__device__ float g_cls [cB*cD];
// bf16 split buffers (16B-aligned for uint4 loads). 3-term split: 3x columns.
__device__ __align__(16) __nv_bfloat16 g_abf[(size_t)cM*3*cFF];
__device__ __align__(16) __nv_bfloat16 g_wt [(size_t)cFF*3*cD];

// ---------------- cp.async helpers ----------------
__device__ __forceinline__ void cp_async16(void* smem_dst, const void* gmem_src, bool valid) {
    unsigned dst = (unsigned)__cvta_generic_to_shared(smem_dst);
    int sz = valid ? 16 : 0;
    asm volatile("cp.async.cg.shared.global [%0], [%1], 16, %2;"
                 :: "r"(dst), "l"(gmem_src), "r"(sz));
}
__device__ __forceinline__ void cp_commit() {
    asm volatile("cp.async.commit_group;");
}
template<int N>
__device__ __forceinline__ void cp_wait() {
    asm volatile("cp.async.wait_group %0;" :: "n"(N));
}

// ---------------- 3-term split conversions ----------------
// Activation split: fp32 X[R][C] -> bf16 Y[R][3C] = [hi | lo | hi]
__global__ void split_rows_a_k(const float* __restrict__ X, __nv_bfloat16* __restrict__ Y,
                               int R, int C)
{
    int i = blockIdx.x * 256 + threadIdx.x;
    if (i >= R * C) return;
    int r = i / C, c = i % C;
    float x = X[i];
    __nv_bfloat16 hi = __float2bfloat16(x);
    __nv_bfloat16 lo = __float2bfloat16(x - __bfloat162float(hi));
    size_t base = (size_t)r * (3 * C);
    Y[base + c]         = hi;
    Y[base + C + c]     = lo;
    Y[base + 2 * C + c] = hi;
}

// Weight split (already K-major [N][K]): fp32 W[N][K] -> bf16 Y[N][3K] = [hi | hi | lo]
__global__ void split_rows_w_k(const float* __restrict__ W, __nv_bfloat16* __restrict__ Y,
                               int N, int K)
{
    int i = blockIdx.x * 256 + threadIdx.x;
    if (i >= N * K) return;
    int n = i / K, k = i % K;
    float x = W[i];
    __nv_bfloat16 hi = __float2bfloat16(x);
    __nv_bfloat16 lo = __float2bfloat16(x - __bfloat162float(hi));
    size_t base = (size_t)n * (3 * K);
    Y[base + k]         = hi;
    Y[base + K + k]     = hi;
    Y[base + 2 * K + k] = lo;
}

// Weight transpose+split: fp32 W[K][N] -> bf16 Bt[N][3K] = [hi | hi | lo]
__global__ void split_transpose_k(const float* __restrict__ W, __nv_bfloat16* __restrict__ Bt,
                                  int K, int N)
{
    __shared__ float sm[32][33];
    int k0 = blockIdx.y * 32, n0 = blockIdx.x * 32;
    int tx = threadIdx.x, ty = threadIdx.y;   // 32 x 8
#pragma unroll
    for (int i = 0; i < 4; i++) {
        int k = k0 + ty + i * 8, n = n0 + tx;
        sm[ty + i * 8][tx] = (k < K && n < N) ? W[(size_t)k * N + n] : 0.f;
    }
    __syncthreads();
#pragma unroll
    for (int i = 0; i < 4; i++) {
        int n = n0 + ty + i * 8, k = k0 + tx;
        if (n < N && k < K) {
            float v = sm[tx][ty + i * 8];
            __nv_bfloat16 hi = __float2bfloat16(v);
            __nv_bfloat16 lo = __float2bfloat16(v - __bfloat162float(hi));
            size_t base = (size_t)n * (3 * K);
            Bt[base + k]         = hi;
            Bt[base + K + k]     = hi;
            Bt[base + 2 * K + k] = lo;
        }
    }
}

// ---------------- tensor-core GEMM: C(MxN) = A[M][K3] @ Bt[N][K3]^T + epilogue ----------------
// Both operands bf16 K-major. 128x128 block, 8 warps (2x4) of 64x32, BK=32.
// 2-stage cp.async double-buffered pipeline.
#define TSTR 40   // smem row stride (bf16 elems)
template<int EPI>   // 0: bias; 1: bias+residual; 2: bias+gelu(exact)
__launch_bounds__(256)
__global__ void tgemm_k(const __nv_bfloat16* __restrict__ A, const __nv_bfloat16* __restrict__ Bt,
                        const float* __restrict__ bias, const float* __restrict__ res,
                        float* __restrict__ C, int M, int N, int K2)
{
    __shared__ __align__(16) __nv_bfloat16 As[2][128 * TSTR];
    __shared__ __align__(16) __nv_bfloat16 Bs[2][128 * TSTR];
    const int bm = blockIdx.y * 128, bn = blockIdx.x * 128;
    const int tid = threadIdx.x;
    const int w = tid >> 5, lane = tid & 31;
    const int wm = (w >> 2) * 64, wn = (w & 3) * 32;
    const int grp = lane >> 2, tig = lane & 3;

    // per-thread load coordinates (4 x 16B per tile: 2 for A, 2 for B)
    const int lrow0 = tid >> 2;            // 0..63   (it=0)
    const int lrow1 = 64 + (tid >> 2);     // 64..127 (it=1)
    const int lseg  = (tid & 3) * 8;       // bf16 elem offset within 32-elem k-tile

    float acc[4][4][4];
#pragma unroll
    for (int mi = 0; mi < 4; mi++)
#pragma unroll
        for (int nj = 0; nj < 4; nj++)
#pragma unroll
            for (int r = 0; r < 4; r++) acc[mi][nj][r] = 0.f;

    const int nT = K2 >> 5;   // K2 % 32 == 0 always here

    // prefetch tile 0 into buffer 0
    {
        const int k0 = 0;
        cp_async16(&As[0][lrow0 * TSTR + lseg], A  + (size_t)(bm + lrow0) * K2 + k0 + lseg, bm + lrow0 < M);
        cp_async16(&As[0][lrow1 * TSTR + lseg], A  + (size_t)(bm + lrow1) * K2 + k0 + lseg, bm + lrow1 < M);
        cp_async16(&Bs[0][lrow0 * TSTR + lseg], Bt + (size_t)(bn + lrow0) * K2 + k0 + lseg, bn + lrow0 < N);
        cp_async16(&Bs[0][lrow1 * TSTR + lseg], Bt + (size_t)(bn + lrow1) * K2 + k0 + lseg, bn + lrow1 < N);
        cp_commit();
    }

    for (int t = 0; t < nT; t++) {
        const int cur = t & 1;
        if (t + 1 < nT) {
            const int nxt = cur ^ 1;
            const int k0 = (t + 1) << 5;
            cp_async16(&As[nxt][lrow0 * TSTR + lseg], A  + (size_t)(bm + lrow0) * K2 + k0 + lseg, bm + lrow0 < M);
            cp_async16(&As[nxt][lrow1 * TSTR + lseg], A  + (size_t)(bm + lrow1) * K2 + k0 + lseg, bm + lrow1 < M);
            cp_async16(&Bs[nxt][lrow0 * TSTR + lseg], Bt + (size_t)(bn + lrow0) * K2 + k0 + lseg, bn + lrow0 < N);
            cp_async16(&Bs[nxt][lrow1 * TSTR + lseg], Bt + (size_t)(bn + lrow1) * K2 + k0 + lseg, bn + lrow1 < N);
            cp_commit();
            cp_wait<1>();
        } else {
            cp_wait<0>();
        }
        __syncthreads();

#pragma unroll
        for (int ks = 0; ks < 2; ks++) {
            const int kb = ks * 16;
            unsigned afr[4][4], bfr[4][2];
#pragma unroll
            for (int mi = 0; mi < 4; mi++) {
                const __nv_bfloat16* ap = &As[cur][(wm + mi * 16 + grp) * TSTR + kb + tig * 2];
                afr[mi][0] = *reinterpret_cast<const unsigned*>(ap);
                afr[mi][1] = *reinterpret_cast<const unsigned*>(ap + 8 * TSTR);
                afr[mi][2] = *reinterpret_cast<const unsigned*>(ap + 8);
                afr[mi][3] = *reinterpret_cast<const unsigned*>(ap + 8 * TSTR + 8);
            }
#pragma unroll
            for (int nj = 0; nj < 4; nj++) {
                const __nv_bfloat16* bp = &Bs[cur][(wn + nj * 8 + grp) * TSTR + kb + tig * 2];
                bfr[nj][0] = *reinterpret_cast<const unsigned*>(bp);
                bfr[nj][1] = *reinterpret_cast<const unsigned*>(bp + 8);
            }
#pragma unroll
            for (int mi = 0; mi < 4; mi++)
#pragma unroll
                for (int nj = 0; nj < 4; nj++) {
                    asm volatile(
                        "mma.sync.aligned.m16n8k16.row.col.f32.bf16.bf16.f32 "
                        "{%0,%1,%2,%3}, {%4,%5,%6,%7}, {%8,%9}, {%0,%1,%2,%3};"
                        : "+f"(acc[mi][nj][0]), "+f"(acc[mi][nj][1]),
                          "+f"(acc[mi][nj][2]), "+f"(acc[mi][nj][3])
                        : "r"(afr[mi][0]), "r"(afr[mi][1]), "r"(afr[mi][2]), "r"(afr[mi][3]),
                          "r"(bfr[nj][0]), "r"(bfr[nj][1]));
                }
        }
        __syncthreads();
    }

    // epilogue: c0,c1 -> (row, col), (row, col+1); c2,c3 -> (row+8, col), (row+8, col+1)
#pragma unroll
    for (int mi = 0; mi < 4; mi++) {
#pragma unroll
        for (int nj = 0; nj < 4; nj++) {
            int row0 = bm + wm + mi * 16 + grp;
            int col0 = bn + wn + nj * 8 + tig * 2;
#pragma unroll
            for (int half = 0; half < 2; half++) {
                int row = row0 + half * 8;
                if (row >= M) continue;
#pragma unroll
                for (int qq = 0; qq < 2; qq++) {
                    int col = col0 + qq;
                    if (col >= N) continue;
                    float v = acc[mi][nj][half * 2 + qq] + bias[col];
                    if (EPI == 1) v += res[(size_t)row * N + col];
                    if (EPI == 2) v = 0.5f * v * (1.0f + erff(v * 0.70710678118654752440f));
                    C[(size_t)row * N + col] = v;
                }
            }
        }
    }
}

// ---------------- scalar fp32 GEMM (head only) ----------------
template<int EPI>
__launch_bounds__(256)
__global__ void sgemm_k(const float* __restrict__ A, const float* __restrict__ Bm,
                        const float* __restrict__ bias, const float* __restrict__ res,
                        float* __restrict__ C, int M, int N, int K)
{
    __shared__ float As[8][132];
    __shared__ float Bs[8][132];
    const int bm = blockIdx.y * 128, bn = blockIdx.x * 128;
    const int tid = threadIdx.x;
    const int tx = tid & 15, ty = tid >> 4;
    const int am  = tid >> 1;
    const int ak  = (tid & 1) * 4;
    const int bk  = tid >> 5;
    const int bn4 = (tid & 31) * 4;

    float acc[8][8];
#pragma unroll
    for (int i = 0; i < 8; i++)
#pragma unroll
        for (int j = 0; j < 8; j++) acc[i][j] = 0.f;

    for (int k0 = 0; k0 < K; k0 += 8) {
        float4 a4 = make_float4(0.f, 0.f, 0.f, 0.f);
        if (bm + am < M)
            a4 = *reinterpret_cast<const float4*>(A + (size_t)(bm + am) * K + k0 + ak);
        As[ak+0][am] = a4.x; As[ak+1][am] = a4.y; As[ak+2][am] = a4.z; As[ak+3][am] = a4.w;

        float4 b4 = make_float4(0.f, 0.f, 0.f, 0.f);
        if (bn + bn4 < N)
            b4 = *reinterpret_cast<const float4*>(Bm + (size_t)(k0 + bk) * N + bn + bn4);
        *reinterpret_cast<float4*>(&Bs[bk][bn4]) = b4;
        __syncthreads();

#pragma unroll
        for (int kk = 0; kk < 8; kk++) {
            float a[8], b[8];
            float4 t0 = *reinterpret_cast<const float4*>(&As[kk][ty*8]);
            float4 t1 = *reinterpret_cast<const float4*>(&As[kk][ty*8+4]);
            a[0]=t0.x; a[1]=t0.y; a[2]=t0.z; a[3]=t0.w;
            a[4]=t1.x; a[5]=t1.y; a[6]=t1.z; a[7]=t1.w;
            float4 u0 = *reinterpret_cast<const float4*>(&Bs[kk][tx*8]);
            float4 u1 = *reinterpret_cast<const float4*>(&Bs[kk][tx*8+4]);
            b[0]=u0.x; b[1]=u0.y; b[2]=u0.z; b[3]=u0.w;
            b[4]=u1.x; b[5]=u1.y; b[6]=u1.z; b[7]=u1.w;
#pragma unroll
            for (int i = 0; i < 8; i++)
#pragma unroll
                for (int j = 0; j < 8; j++)
                    acc[i][j] += a[i] * b[j];
        }
        __syncthreads();
    }

#pragma unroll
    for (int i = 0; i < 8; i++) {
        int m = bm + ty*8 + i;
        if (m >= M) continue;
#pragma unroll
        for (int j = 0; j < 8; j++) {
            int n = bn + tx*8 + j;
            if (n >= N) continue;
            float v = acc[i][j] + bias[n];
            if (EPI == 1) v += res[(size_t)m * N + n];
            if (EPI == 2) v = 0.5f * v * (1.0f + erff(v * 0.70710678118654752440f));
            C[(size_t)m * N + n] = v;
        }
    }
}

// ---------------- batched GEMM (attention) ----------------
__launch_bounds__(256)
__global__ void bgemm_k(const float* __restrict__ Ag, const float* __restrict__ Bg,
                        float* __restrict__ Cg, int M, int N, int K,
                        long sA, long sB, long sC, float alpha)
{
    const float* A = Ag + (size_t)blockIdx.z * sA;
    const float* Bm = Bg + (size_t)blockIdx.z * sB;
    float* C = Cg + (size_t)blockIdx.z * sC;
    __shared__ float As[16][68];
    __shared__ float Bs[16][68];
    const int bm = blockIdx.y * 64, bn = blockIdx.x * 64;
    const int tid = threadIdx.x;
    const int tx = tid & 15, ty = tid >> 4;
    const int am = tid >> 2, ak = (tid & 3) * 4;
    const int bk = tid >> 4, bn4 = (tid & 15) * 4;
    float acc[4][4] = {};

    for (int k0 = 0; k0 < K; k0 += 16) {
#pragma unroll
        for (int c = 0; c < 4; c++) {
            int k = k0 + ak + c;
            As[ak+c][am] = (bm + am < M && k < K) ? A[(size_t)(bm+am)*K + k] : 0.f;
        }
#pragma unroll
        for (int c = 0; c < 4; c++) {
            int n = bn + bn4 + c;
            Bs[bk][bn4+c] = (k0 + bk < K && n < N) ? Bm[(size_t)(k0+bk)*N + n] : 0.f;
        }
        __syncthreads();
#pragma unroll
        for (int kk = 0; kk < 16; kk++) {
            float a[4], b[4];
#pragma unroll
            for (int i = 0; i < 4; i++) a[i] = As[kk][ty*4+i];
#pragma unroll
            for (int j = 0; j < 4; j++) b[j] = Bs[kk][tx*4+j];
#pragma unroll
            for (int i = 0; i < 4; i++)
#pragma unroll
                for (int j = 0; j < 4; j++)
                    acc[i][j] += a[i] * b[j];
        }
        __syncthreads();
    }
#pragma unroll
    for (int i = 0; i < 4; i++) {
        int m = bm + ty*4 + i;
        if (m >= M) continue;
#pragma unroll
        for (int j = 0; j < 4; j++) {
            int n = bn + tx*4 + j;
            if (n < N) C[(size_t)m*N + n] = alpha * acc[i][j];
        }
    }
}

// ---------------- small kernels ----------------
__global__ void im2col_k(const float* __restrict__ x, float* __restrict__ col)
{
    int t = blockIdx.x * 256 + threadIdx.x;
    if (t >= cMP * cD) return;
    int m = t / cD, k = t % cD;
    int b = m / cNP, p = m % cNP;
    int gy = p / cG, gx = p % cG;
    int c = k >> 8, r = k & 255;
    int py = r >> 4, px = r & 15;
    col[t] = x[(((size_t)b * cCh + c) * cHW + gy * cP + py) * cHW + gx * cP + px];
}

__global__ void pooled_k(const float* __restrict__ x, float* __restrict__ pooled)
{
    int bp = blockIdx.x;
    int b = bp / cNP, p = bp % cNP;
    int gy = p / cG, gx = p % cG;
    int t = threadIdx.x;
    int py = t >> 4, px = t & 15;
    float v = x[((size_t)b * cCh) * cHW * cHW + (size_t)(gy * cP + py) * cHW + gx * cP + px];
    __shared__ float sm[256];
    sm[t] = v; __syncthreads();
    for (int s = 128; s; s >>= 1) { if (t < s) sm[t] += sm[t + s]; __syncthreads(); }
    if (t == 0) pooled[bp] = sm[0] * (1.f / 256.f);
}

__global__ void topk_k(const float* __restrict__ pooled, int* __restrict__ idx)
{
    int b = blockIdx.x;
    __shared__ float key[1024];
    __shared__ int   sid[1024];
    int t = threadIdx.x;  // 512
    for (int i = t; i < 1024; i += 512) {
        if (i < cNP) { key[i] = fabsf(pooled[b * cNP + i]); sid[i] = i; }
        else         { key[i] = -1.f; sid[i] = i; }
    }
    __syncthreads();
    for (int k = 2; k <= 1024; k <<= 1) {
        for (int j = k >> 1; j > 0; j >>= 1) {
            for (int i = t; i < 1024; i += 512) {
                int ixj = i ^ j;
                if (ixj > i) {
                    bool asc = (i & k) != 0;
                    float ki = key[i], kj = key[ixj];
                    bool sw = asc ? (ki > kj) : (ki < kj);
                    if (sw) {
                        key[i] = kj; key[ixj] = ki;
                        int tmp = sid[i]; sid[i] = sid[ixj]; sid[ixj] = tmp;
                    }
                }
            }
            __syncthreads();
        }
    }
    for (int i = t; i < cKsel; i += 512) idx[b * cKsel + i] = sid[i];
}

__global__ void build_h_k(const float* __restrict__ pemb, const int* __restrict__ idx,
                          const float* __restrict__ cls_tok, const float* __restrict__ pos,
                          float* __restrict__ h)
{
    int row = blockIdx.x;
    int b = row / cS, s = row % cS;
    int t = threadIdx.x;
    float* hp = h + (size_t)row * cD;
    if (s == 0) {
        for (int d = t; d < cD; d += 256) hp[d] = cls_tok[d] + pos[d];
    } else {
        int p = idx[b * cKsel + s - 1];
        const float* src = pemb + (size_t)(b * cNP + p) * cD;
        const float* pp  = pos + (size_t)(1 + p) * cD;
        for (int d = t; d < cD; d += 256) hp[d] = src[d] + pp[d];
    }
}

__global__ void layernorm_k(const float* __restrict__ X, long rowStride,
                            const float* __restrict__ g, const float* __restrict__ bb,
                            float* __restrict__ Y, long outStride)
{
    int row = blockIdx.x, t = threadIdx.x;
    const float* xp = X + (size_t)row * rowStride;
    float v0 = xp[t], v1 = xp[t + 256], v2 = xp[t + 512];
    __shared__ float sm[256];
    sm[t] = v0 + v1 + v2; __syncthreads();
    for (int s = 128; s; s >>= 1) { if (t < s) sm[t] += sm[t + s]; __syncthreads(); }
    float mean = sm[0] * (1.f / 768.f); __syncthreads();
    float d0 = v0 - mean, d1 = v1 - mean, d2 = v2 - mean;
    sm[t] = d0*d0 + d1*d1 + d2*d2; __syncthreads();
    for (int s = 128; s; s >>= 1) { if (t < s) sm[t] += sm[t + s]; __syncthreads(); }
    float inv = rsqrtf(sm[0] * (1.f / 768.f) + 1e-6f);
    float* yp = Y + (size_t)row * outStride;
    yp[t]       = d0 * inv * g[t]       + bb[t];
    yp[t + 256] = d1 * inv * g[t + 256] + bb[t + 256];
    yp[t + 512] = d2 * inv * g[t + 512] + bb[t + 512];
}

__global__ void reshape_qkv_k(const float* __restrict__ qkv, float* __restrict__ q,
                              float* __restrict__ kt, float* __restrict__ v)
{
    int t = blockIdx.x * 256 + threadIdx.x;
    if (t >= cM * cD) return;
    int row = t / cD, c = t % cD;
    int b = row / cS, s = row % cS;
    int hh = c / cHD, d = c % cHD;
    size_t base = (size_t)row * (3 * cD);
    int bh = b * cNH + hh;
    q [((size_t)bh * cS + s) * cHD + d] = qkv[base + c];
    kt[((size_t)bh * cHD + d) * cS + s] = qkv[base + cD + c];
    v [((size_t)bh * cS + s) * cHD + d] = qkv[base + 2 * cD + c];
}

__global__ void reshape_o_k(const float* __restrict__ o, float* __restrict__ orr)
{
    int t = blockIdx.x * 256 + threadIdx.x;
    if (t >= cM * cD) return;
    int row = t / cD, c = t % cD;
    int b = row / cS, s = row % cS;
    int hh = c / cHD, d = c % cHD;
    orr[t] = o[(((size_t)(b * cNH + hh)) * cS + s) * cHD + d];
}

__global__ void softmax_k(float* __restrict__ att)
{
    int row = blockIdx.x;
    float* p = att + (size_t)row * cS;
    int t = threadIdx.x;
    __shared__ float sm[256];
    float v0 = (t < cS)       ? p[t]       : -3.4e38f;
    float v1 = (t + 256 < cS) ? p[t + 256] : -3.4e38f;
    sm[t] = fmaxf(v0, v1); __syncthreads();
    for (int s = 128; s; s >>= 1) { if (t < s) sm[t] = fmaxf(sm[t], sm[t + s]); __syncthreads(); }
    float mx = sm[0]; __syncthreads();
    float e0 = (t < cS)       ? expf(v0 - mx) : 0.f;
    float e1 = (t + 256 < cS) ? expf(v1 - mx) : 0.f;
    sm[t] = e0 + e1; __syncthreads();
    for (int s = 128; s; s >>= 1) { if (t < s) sm[t] += sm[t + s]; __syncthreads(); }
    float inv = 1.f / sm[0];
    if (t < cS)       p[t]       = e0 * inv;
    if (t + 256 < cS) p[t + 256] = e1 * inv;
}

// ---------------- driver ----------------
static inline dim3 tgrid(int M, int N) { return dim3((N + 127) / 128, (M + 127) / 128); }

extern "C" void kernel_launch(void* const* d_in, const int* in_sizes, int n_in,
                              void* d_out, int out_size)
{
    const float* x       = (const float*)d_in[0];
    const float* patch_w = (const float*)d_in[1];
    const float* patch_b = (const float*)d_in[2];
    const float* cls_tok = (const float*)d_in[3];
    const float* pos_emb = (const float*)d_in[4];
    const float* ln1_g   = (const float*)d_in[5];
    const float* ln1_b   = (const float*)d_in[6];
    const float* Wqkv    = (const float*)d_in[7];
    const float* bqkv    = (const float*)d_in[8];
    const float* Wo      = (const float*)d_in[9];
    const float* bo      = (const float*)d_in[10];
    const float* ln2_g   = (const float*)d_in[11];
    const float* ln2_b   = (const float*)d_in[12];
    const float* W1      = (const float*)d_in[13];
    const float* b1      = (const float*)d_in[14];
    const float* W2      = (const float*)d_in[15];
    const float* b2      = (const float*)d_in[16];
    const float* lnf_g   = (const float*)d_in[17];
    const float* lnf_b   = (const float*)d_in[18];
    const float* fc_w    = (const float*)d_in[19];
    const float* fc_b    = (const float*)d_in[20];
    float* out = (float*)d_out;

    float *col, *pemb, *pooled, *h, *y, *qkv, *q, *kt, *v, *att, *o, *orr, *ffn, *cls;
    __nv_bfloat16 *abf, *wt;
    int* idx;
    cudaGetSymbolAddress((void**)&col,    g_col);
    cudaGetSymbolAddress((void**)&pemb,   g_pemb);
    cudaGetSymbolAddress((void**)&pooled, g_pooled);
    cudaGetSymbolAddress((void**)&idx,    g_idx);
    cudaGetSymbolAddress((void**)&h,      g_h);
    cudaGetSymbolAddress((void**)&y,      g_y);
    cudaGetSymbolAddress((void**)&qkv,    g_qkv);
    cudaGetSymbolAddress((void**)&q,      g_q);
    cudaGetSymbolAddress((void**)&kt,     g_kt);
    cudaGetSymbolAddress((void**)&v,      g_v);
    cudaGetSymbolAddress((void**)&att,    g_att);
    cudaGetSymbolAddress((void**)&o,      g_o);
    cudaGetSymbolAddress((void**)&orr,    g_or);
    cudaGetSymbolAddress((void**)&ffn,    g_ffn);
    cudaGetSymbolAddress((void**)&cls,    g_cls);
    cudaGetSymbolAddress((void**)&abf,    g_abf);
    cudaGetSymbolAddress((void**)&wt,     g_wt);

    const dim3 tt(32, 8);

    // patch embed: col[9216][768] @ patch_w^T  (patch_w is [768 out][768 in] = [N][K] already)
    im2col_k<<<(cMP*cD + 255)/256, 256>>>(x, col);
    split_rows_a_k<<<(cMP*cD + 255)/256, 256>>>(col, abf, cMP, cD);
    split_rows_w_k<<<(cD*cD + 255)/256, 256>>>(patch_w, wt, cD, cD);
    tgemm_k<0><<<tgrid(cMP, cD), 256>>>(abf, wt, patch_b, nullptr, pemb, cMP, cD, 3*cD);

    // token selection
    pooled_k<<<cMP, 256>>>(x, pooled);
    topk_k<<<cB, 512>>>(pooled, idx);
    build_h_k<<<cM, 256>>>(pemb, idx, cls_tok, pos_emb, h);

    // transformer layers
    for (int l = 0; l < cNL; l++) {
        layernorm_k<<<cM, 256>>>(h, cD, ln1_g + (size_t)l*cD, ln1_b + (size_t)l*cD, y, cD);
        split_rows_a_k<<<(cM*cD + 255)/256, 256>>>(y, abf, cM, cD);
        split_transpose_k<<<dim3((3*cD+31)/32, (cD+31)/32), tt>>>(Wqkv + (size_t)l*cD*3*cD, wt, cD, 3*cD);
        tgemm_k<0><<<tgrid(cM, 3*cD), 256>>>(abf, wt, bqkv + (size_t)l*3*cD, nullptr, qkv, cM, 3*cD, 3*cD);

        reshape_qkv_k<<<(cM*cD + 255)/256, 256>>>(qkv, q, kt, v);
        bgemm_k<<<dim3((cS+63)/64, (cS+63)/64, cBH), 256>>>(
            q, kt, att, cS, cS, cHD, (long)cS*cHD, (long)cHD*cS, (long)cS*cS, 0.125f);
        softmax_k<<<cBH*cS, 256>>>(att);
        bgemm_k<<<dim3(1, (cS+63)/64, cBH), 256>>>(
            att, v, o, cS, cHD, cS, (long)cS*cS, (long)cS*cHD, (long)cS*cHD, 1.0f);
        reshape_o_k<<<(cM*cD + 255)/256, 256>>>(o, orr);

        split_rows_a_k<<<(cM*cD + 255)/256, 256>>>(orr, abf, cM, cD);
        split_transpose_k<<<dim3((cD+31)/32, (cD+31)/32), tt>>>(Wo + (size_t)l*cD*cD, wt, cD, cD);
        tgemm_k<1><<<tgrid(cM, cD), 256>>>(abf, wt, bo + (size_t)l*cD, h, h, cM, cD, 3*cD);

        layernorm_k<<<cM, 256>>>(h, cD, ln2_g + (size_t)l*cD, ln2_b + (size_t)l*cD, y, cD);
        split_rows_a_k<<<(cM*cD + 255)/256, 256>>>(y, abf, cM, cD);
        split_transpose_k<<<dim3((cFF+31)/32, (cD+31)/32), tt>>>(W1 + (size_t)l*cD*cFF, wt, cD, cFF);
        tgemm_k<2><<<tgrid(cM, cFF), 256>>>(abf, wt, b1 + (size_t)l*cFF, nullptr, ffn, cM, cFF, 3*cD);

        split_rows_a_k<<<(cM*cFF + 255)/256, 256>>>(ffn, abf, cM, cFF);
        split_transpose_k<<<dim3((cD+31)/32, (cFF+31)/32), tt>>>(W2 + (size_t)l*cFF*cD, wt, cFF, cD);
        tgemm_k<1><<<tgrid(cM, cD), 256>>>(abf, wt, b2 + (size_t)l*cD, h, h, cM, cD, 3*cFF);
    }

    // head (tiny — scalar fp32)
    layernorm_k<<<cB, 256>>>(h, (long)cS*cD, lnf_g, lnf_b, cls, cD);
    sgemm_k<0><<<dim3((cNCLS+127)/128, 1), 256>>>(cls, fc_w, fc_b, nullptr, out, cB, cNCLS, cD);
}